// round 17
// baseline (speedup 1.0000x reference)
#include <cuda_runtime.h>
#include <cuda_bf16.h>
#include <cstdint>

// Flatten 2x2 blocks:
//   out[bc, i*1024 + 4j + 2r + s] = x[bc, 2i+r, 2j+s]
// x: (32, 3, 512, 512) fp32. bc in [0,96), i in [0,256), j in [0,256).
//
// R17: bulk-async write combining at the confirmed geometry optimum
// (3072 CTAs x 1024 threads, contiguous 32 KB strips). Each CTA stages
// its permuted 32 KB output strip in SMEM, then ONE elected thread emits
// a single cp.async.bulk.global.shared::cta (32 KB write burst through
// the async proxy). Separates the read phase from the write phase per
// CTA and collapses 2048 STGs into one bulk op -> fewer DRAM R/W
// turnarounds. Loads unchanged: 2 coalesced LDG.128 per thread.

__global__ __launch_bounds__(1024)
void flatten2x2_kernel(const float4* __restrict__ x4, float4* __restrict__ out4) {
    __shared__ alignas(128) float4 s[2048];     // 32 KB = one output strip

    unsigned tid = threadIdx.x;                 // 0..1023
    unsigned j0  = tid & 127u;                  // j-pair index: j = 2*j0, 2*j0+1
    unsigned di  = tid >> 7;                    // 0..7: i slot within strip
    unsigned blk = blockIdx.x;                  // 0..3071
    unsigned i   = (blk & 31u) * 8u + di;       // i in [0,256)
    unsigned bc  = blk >> 5;                    // 0..95

    // input as float4: row stride 128, image stride 512*128 = 65536
    const float4* base = x4 + (size_t)bc * 65536u + (size_t)(2u * i) * 128u + j0;
    float4 a = __ldg(base);          // row 2i,   cols 4j0..4j0+3
    float4 b = __ldg(base + 128u);   // row 2i+1, cols 4j0..4j0+3

    // stage into SMEM, laid out exactly as the contiguous output strip:
    // strip-local float4 index = di*256 + 2*j0 (+1)
    unsigned so = di * 256u + 2u * j0;
    s[so]      = make_float4(a.x, a.y, b.x, b.y);   // out f4 (i, 2j0)
    s[so + 1u] = make_float4(a.z, a.w, b.z, b.w);   // out f4 (i, 2j0+1)

    __syncthreads();

    if (tid == 0) {
        // order the generic-proxy SMEM writes before the async-proxy read
        asm volatile("fence.proxy.async.shared::cta;" ::: "memory");

        // strip base in gmem: image bc, i in [ (blk&31)*8, +8 )
        float4* dst = out4 + (size_t)bc * 65536u + (size_t)(blk & 31u) * 2048u;
        uint32_t saddr;
        asm("{ .reg .u64 t; cvta.to.shared.u64 t, %1; cvt.u32.u64 %0, t; }"
            : "=r"(saddr) : "l"(s));

        asm volatile(
            "cp.async.bulk.global.shared::cta.bulk_group [%0], [%1], %2;"
            :: "l"(dst), "r"(saddr), "r"(32768u) : "memory");
        asm volatile("cp.async.bulk.commit_group;" ::: "memory");
        asm volatile("cp.async.bulk.wait_group 0;" ::: "memory");
    }
}

extern "C" void kernel_launch(void* const* d_in, const int* in_sizes, int n_in,
                              void* d_out, int out_size) {
    const float4* x4 = (const float4*)d_in[0];
    float4* out4 = (float4*)d_out;

    // 96 images x 32 strips (8 i-values each) = 3072 CTAs, 1024 threads
    flatten2x2_kernel<<<3072, 1024>>>(x4, out4);
}